// round 1
// baseline (speedup 1.0000x reference)
#include <cuda_runtime.h>

#define BB 2
#define CIN 64
#define CI 16
#define HH 256
#define WWD 256
#define HW (HH*WWD)
#define LL 4096
#define DIN 784
#define DOUT 196

// ---------------- scratch (static device globals; no allocations) ----------------
__device__ float g_b1[(size_t)BB*CI*HW];
__device__ float g_b2[(size_t)BB*CI*HW];
__device__ float g_wi[(size_t)BB*LL*DIN];
__device__ float g_pi[(size_t)BB*LL*DIN];
__device__ float g_wif[(size_t)BB*LL*DOUT];
__device__ float g_xif[(size_t)BB*LL*DOUT];
__device__ float g_thr[BB*LL];
__device__ float g_bv[BB*LL];
__device__ float g_score[(size_t)BB*LL*LL];
__device__ float g_agg[(size_t)BB*LL*DIN];

// ---------------- conv 3x3 (b -> b1), pad 1 ----------------
__global__ __launch_bounds__(256) void conv3x3_k(const float* __restrict__ bin,
    const float* __restrict__ gw, const float* __restrict__ gb)
{
    __shared__ float sw[CI*CIN*9];
    int tid = threadIdx.y*16 + threadIdx.x;
    for (int i = tid; i < CI*CIN*9; i += 256) sw[i] = gw[i];
    __syncthreads();
    int bb = blockIdx.z;
    int x = blockIdx.x*16 + threadIdx.x;
    int y = blockIdx.y*16 + threadIdx.y;
    float acc[CI];
    #pragma unroll
    for (int co = 0; co < CI; co++) acc[co] = gb[co];
    const float* bp = bin + (size_t)bb*CIN*HW;
    bool y0 = (y > 0), y2 = (y < HH-1), x0 = (x > 0), x2 = (x < WWD-1);
    for (int ci = 0; ci < CIN; ci++) {
        const float* c0 = bp + (size_t)ci*HW + y*WWD + x;
        float v[9];
        v[0] = (y0&&x0)? c0[-WWD-1]:0.f; v[1] = y0? c0[-WWD]:0.f; v[2] = (y0&&x2)? c0[-WWD+1]:0.f;
        v[3] = x0? c0[-1]:0.f;           v[4] = c0[0];            v[5] = x2? c0[1]:0.f;
        v[6] = (y2&&x0)? c0[WWD-1]:0.f;  v[7] = y2? c0[WWD]:0.f;  v[8] = (y2&&x2)? c0[WWD+1]:0.f;
        #pragma unroll
        for (int co = 0; co < CI; co++) {
            const float* w = &sw[(co*CIN+ci)*9];
            float a = acc[co];
            #pragma unroll
            for (int t = 0; t < 9; t++) a += v[t]*w[t];
            acc[co] = a;
        }
    }
    #pragma unroll
    for (int co = 0; co < CI; co++)
        g_b1[(size_t)(bb*CI+co)*HW + y*WWD + x] = acc[co];
}

// ---------------- conv 1x1 (b -> b2) ----------------
__global__ __launch_bounds__(256) void conv1x1_k(const float* __restrict__ bin,
    const float* __restrict__ tw, const float* __restrict__ tb)
{
    __shared__ float sw[CI*CIN];
    int tid = threadIdx.x;
    for (int i = tid; i < CI*CIN; i += 256) sw[i] = tw[i];
    __syncthreads();
    int p = blockIdx.x*256 + tid;
    int bb = blockIdx.y;
    const float* bp = bin + (size_t)bb*CIN*HW + p;
    float acc[CI];
    #pragma unroll
    for (int co = 0; co < CI; co++) acc[co] = tb[co];
    for (int ci = 0; ci < CIN; ci++) {
        float v = bp[(size_t)ci*HW];
        #pragma unroll
        for (int co = 0; co < CI; co++) acc[co] += v * sw[co*CIN+ci];
    }
    #pragma unroll
    for (int co = 0; co < CI; co++)
        g_b2[(size_t)(bb*CI+co)*HW + p] = acc[co];
}

// ---------------- thr/bias 7x7 stride-4 convs (padded SAME) ----------------
__global__ __launch_bounds__(256) void thrbias_k(const float* __restrict__ bin,
    const float* __restrict__ tw, const float* __restrict__ tb,
    const float* __restrict__ bw, const float* __restrict__ bwb)
{
    __shared__ float swt[CIN*49], swb[CIN*49];
    int tid = threadIdx.x;
    for (int i = tid; i < CIN*49; i += 256) { swt[i] = tw[i]; swb[i] = bw[i]; }
    __syncthreads();
    int idx = blockIdx.x*256 + tid;              // b*LL + l
    int bb = idx >> 12;
    int l = idx & (LL-1);
    int r = l >> 6, c = l & 63;
    float at = tb[0], ab = bwb[0];
    const float* bp = bin + (size_t)bb*CIN*HW;
    int ybase = r*4 - 1, xbase = c*4 - 1;        // pad top/left = 1
    for (int ci = 0; ci < CIN; ci++) {
        const float* cp = bp + (size_t)ci*HW;
        #pragma unroll
        for (int di = 0; di < 7; di++) {
            int iy = ybase + di;
            if (iy < 0 || iy >= HH) continue;
            #pragma unroll
            for (int dj = 0; dj < 7; dj++) {
                int ix = xbase + dj;
                if (ix < 0 || ix >= WWD) continue;
                float v = cp[iy*WWD + ix];
                at += v * swt[ci*49 + di*7 + dj];
                ab += v * swb[ci*49 + di*7 + dj];
            }
        }
    }
    g_thr[idx] = at;
    g_bv[idx] = ab;
}

// ---------------- patch extraction: wi from b1 (z=0), pi from b2 (z=1) ----------------
__global__ __launch_bounds__(256) void patches_k()
{
    int t = blockIdx.x*256 + threadIdx.x;        // < BB*LL*DIN
    int d = t % DIN;
    int rest = t / DIN;
    int l = rest & (LL-1);
    int bb = rest >> 12;
    int ci = d / 49, rem = d % 49;
    int di = rem / 7, dj = rem % 7;
    int r = l >> 6, c = l & 63;
    int iy = r*4 + di - 1, ix = c*4 + dj - 1;    // pad = 1 top/left
    float val = 0.f;
    if (iy >= 0 && iy < HH && ix >= 0 && ix < WWD) {
        size_t src = (size_t)(bb*CI+ci)*HW + (size_t)iy*WWD + ix;
        val = (blockIdx.z == 0) ? g_b1[src] : g_b2[src];
    }
    if (blockIdx.z == 0) g_wi[(size_t)t] = val;
    else                 g_pi[(size_t)t] = val;
}

// ---------------- generic 128x128x8 tiled SGEMM ----------------
// C[M,N] = A[M,K] * B (+bias, relu).  TRANSB: B is [N,K] row-major; else [K,N].
// If C2 != nullptr: dual mode — blockIdx.z==1 switches B/bias/C (shared A).
// Else: batched with per-z strides sA/sB/sC.
template<bool TRANSB, bool RELU, bool BIAS>
__global__ __launch_bounds__(256) void gemm_k(
    const float* __restrict__ A, const float* __restrict__ Bm,
    const float* __restrict__ bias, float* __restrict__ C,
    int M, int N, int K,
    long long sA, long long sB, long long sC,
    const float* __restrict__ B2, const float* __restrict__ bias2, float* __restrict__ C2)
{
    int z = blockIdx.z;
    if (C2 != nullptr) {
        if (z == 1) { Bm = B2; bias = bias2; C = C2; }
    } else {
        A  += (size_t)z * sA;
        Bm += (size_t)z * sB;
        C  += (size_t)z * sC;
    }
    __shared__ float As[8][128];
    __shared__ float Bs[8][128];
    int tid = threadIdx.x;
    int tx = tid & 15, ty = tid >> 4;
    int m0 = blockIdx.y * 128, n0 = blockIdx.x * 128;
    float acc[8][8];
    #pragma unroll
    for (int i = 0; i < 8; i++)
        #pragma unroll
        for (int j = 0; j < 8; j++) acc[i][j] = 0.f;

    int lm = tid >> 1;
    int lk = (tid & 1) * 4;
    for (int k0 = 0; k0 < K; k0 += 8) {
        float ra[4], rb[4];
        {
            int gm = m0 + lm;
            #pragma unroll
            for (int j = 0; j < 4; j++) {
                int gk = k0 + lk + j;
                ra[j] = (gm < M && gk < K) ? A[(size_t)gm*K + gk] : 0.f;
            }
        }
        if (TRANSB) {
            int gn = n0 + lm;
            #pragma unroll
            for (int j = 0; j < 4; j++) {
                int gk = k0 + lk + j;
                rb[j] = (gn < N && gk < K) ? Bm[(size_t)gn*K + gk] : 0.f;
            }
        } else {
            #pragma unroll
            for (int j = 0; j < 4; j++) {
                int idx = j*256 + tid;
                int kk = idx >> 7, n = idx & 127;
                int gk = k0 + kk, gn = n0 + n;
                rb[j] = (gk < K && gn < N) ? Bm[(size_t)gk*N + gn] : 0.f;
            }
        }
        __syncthreads();
        #pragma unroll
        for (int j = 0; j < 4; j++) As[lk+j][lm] = ra[j];
        if (TRANSB) {
            #pragma unroll
            for (int j = 0; j < 4; j++) Bs[lk+j][lm] = rb[j];
        } else {
            #pragma unroll
            for (int j = 0; j < 4; j++) { int idx = j*256+tid; Bs[idx>>7][idx&127] = rb[j]; }
        }
        __syncthreads();
        #pragma unroll
        for (int kk = 0; kk < 8; kk++) {
            float av[8], bv[8];
            #pragma unroll
            for (int i = 0; i < 8; i++) av[i] = As[kk][ty*8+i];
            #pragma unroll
            for (int j = 0; j < 8; j++) bv[j] = Bs[kk][tx*8+j];
            #pragma unroll
            for (int i = 0; i < 8; i++)
                #pragma unroll
                for (int j = 0; j < 8; j++)
                    acc[i][j] += av[i]*bv[j];
        }
    }
    #pragma unroll
    for (int i = 0; i < 8; i++) {
        int gm = m0 + ty*8 + i;
        if (gm >= M) continue;
        #pragma unroll
        for (int j = 0; j < 8; j++) {
            int gn = n0 + tx*8 + j;
            if (gn >= N) continue;
            float vv = acc[i][j];
            if (BIAS) vv += bias[gn];
            if (RELU) vv = fmaxf(vv, 0.f);
            C[(size_t)gm*N + gn] = vv;
        }
    }
}

// ---------------- masked softmax + renorm, in-place over g_score rows ----------------
// final_m = mask_m * e^{10(g_m - max)} / (sum_masked e + 1e-8 * Z)   (exact algebra of reference)
__global__ __launch_bounds__(256) void softmax_k()
{
    __shared__ float sh0[8], sh1[8];
    int row = blockIdx.x;                       // b*LL + l
    int tid = threadIdx.x;
    float thr = g_thr[row], bs = g_bv[row];
    float* S = g_score + (size_t)row*LL;
    float g[16];
    unsigned mb = 0;
    float lmax = -3.4e38f;
    #pragma unroll
    for (int i = 0; i < 16; i++) {
        float s = S[i*256 + tid];
        bool m = (s >= thr);
        float gg = (m ? s : 0.f) + bs;
        if (m) mb |= (1u << i);
        g[i] = gg;
        lmax = fmaxf(lmax, gg);
    }
    float v = lmax;
    #pragma unroll
    for (int o = 16; o > 0; o >>= 1) v = fmaxf(v, __shfl_xor_sync(0xffffffffu, v, o));
    if ((tid & 31) == 0) sh0[tid >> 5] = v;
    __syncthreads();
    float M = sh0[0];
    #pragma unroll
    for (int i = 1; i < 8; i++) M = fmaxf(M, sh0[i]);
    __syncthreads();
    float z = 0.f, a = 0.f;
    #pragma unroll
    for (int i = 0; i < 16; i++) {
        float e = __expf(10.f * (g[i] - M));
        z += e;
        float me = ((mb >> i) & 1u) ? e : 0.f;
        a += me;
        g[i] = me;
    }
    float vz = z, va = a;
    #pragma unroll
    for (int o = 16; o > 0; o >>= 1) {
        vz += __shfl_xor_sync(0xffffffffu, vz, o);
        va += __shfl_xor_sync(0xffffffffu, va, o);
    }
    if ((tid & 31) == 0) { sh0[tid >> 5] = vz; sh1[tid >> 5] = va; }
    __syncthreads();
    float Z = 0.f, A = 0.f;
    #pragma unroll
    for (int i = 0; i < 8; i++) { Z += sh0[i]; A += sh1[i]; }
    float inv = 1.f / (A + 1e-8f * Z);
    #pragma unroll
    for (int i = 0; i < 16; i++) S[i*256 + tid] = g[i] * inv;
}

// ---------------- fold (overlap-add gather / count) + 1x1 conv + residual ----------------
__global__ __launch_bounds__(256) void fold_k(const float* __restrict__ bin,
    const float* __restrict__ Ww, const float* __restrict__ Wb,
    float* __restrict__ out)
{
    __shared__ float sw[CIN*CI];
    int tid = threadIdx.x;
    for (int i = tid; i < CIN*CI; i += 256) sw[i] = Ww[i];
    __syncthreads();
    int p = blockIdx.x*256 + tid;
    int bb = blockIdx.y;
    int y = p >> 8, x = p & 255;
    int u = y + 1, v = x + 1;                  // padded coords (crop offset 1)
    int rlo = (u-3) >> 2; if (rlo < 0) rlo = 0;
    int rhi = u >> 2;     if (rhi > 63) rhi = 63;
    int clo = (v-3) >> 2; if (clo < 0) clo = 0;
    int chi = v >> 2;     if (chi > 63) chi = 63;
    float zi[CI];
    #pragma unroll
    for (int ci = 0; ci < CI; ci++) zi[ci] = 0.f;
    for (int r = rlo; r <= rhi; r++) {
        int di = u - r*4;
        for (int c = clo; c <= chi; c++) {
            int dj = v - c*4;
            const float* ap = g_agg + ((size_t)bb*LL + (r<<6) + c)*DIN + di*7 + dj;
            #pragma unroll
            for (int ci = 0; ci < CI; ci++) zi[ci] += ap[ci*49];
        }
    }
    float inv = 1.f / (float)((rhi-rlo+1)*(chi-clo+1));
    #pragma unroll
    for (int ci = 0; ci < CI; ci++) zi[ci] *= inv;
    const float* bp = bin + (size_t)bb*CIN*HW + p;
    float* op = out + (size_t)bb*CIN*HW + p;
    #pragma unroll 4
    for (int co = 0; co < CIN; co++) {
        float a = bp[(size_t)co*HW] + Wb[co];
        const float* w = &sw[co*CI];
        #pragma unroll
        for (int ci = 0; ci < CI; ci++) a += w[ci]*zi[ci];
        op[(size_t)co*HW] = a;
    }
}

// ---------------- launch ----------------
extern "C" void kernel_launch(void* const* d_in, const int* in_sizes, int n_in,
                              void* d_out, int out_size)
{
    const float* b       = (const float*)d_in[0];
    const float* g_w     = (const float*)d_in[1];
    const float* g_bias  = (const float*)d_in[2];
    const float* theta_w = (const float*)d_in[3];
    const float* theta_b = (const float*)d_in[4];
    const float* W_w     = (const float*)d_in[5];
    const float* W_b     = (const float*)d_in[6];
    const float* fc1_w   = (const float*)d_in[7];
    const float* fc1_b   = (const float*)d_in[8];
    const float* fc2_w   = (const float*)d_in[9];
    const float* fc2_b   = (const float*)d_in[10];
    const float* thr_w   = (const float*)d_in[11];
    const float* thr_b   = (const float*)d_in[12];
    const float* bias_w  = (const float*)d_in[13];
    const float* bias_b  = (const float*)d_in[14];

    float *p_wi, *p_pi, *p_wif, *p_xif, *p_score, *p_agg;
    cudaGetSymbolAddress((void**)&p_wi,    g_wi);
    cudaGetSymbolAddress((void**)&p_pi,    g_pi);
    cudaGetSymbolAddress((void**)&p_wif,   g_wif);
    cudaGetSymbolAddress((void**)&p_xif,   g_xif);
    cudaGetSymbolAddress((void**)&p_score, g_score);
    cudaGetSymbolAddress((void**)&p_agg,   g_agg);

    conv3x3_k<<<dim3(16,16,BB), dim3(16,16)>>>(b, g_w, g_bias);
    conv1x1_k<<<dim3(HW/256, BB), 256>>>(b, theta_w, theta_b);
    thrbias_k<<<(BB*LL)/256, 256>>>(b, thr_w, thr_b, bias_w, bias_b);
    patches_k<<<dim3((BB*LL*DIN)/256, 1, 2), 256>>>();

    // fc1 & fc2 fused via dual mode: M=8192, N=196, K=784, bias+relu
    gemm_k<true, true, true><<<dim3(2, 64, 2), 256>>>(
        p_wi, fc1_w, fc1_b, p_wif, BB*LL, DOUT, DIN,
        0, 0, 0, fc2_w, fc2_b, p_xif);

    // score = wif @ xif^T  per batch: M=N=4096, K=196
    gemm_k<true, false, false><<<dim3(32, 32, BB), 256>>>(
        p_wif, p_xif, nullptr, p_score, LL, LL, DOUT,
        (long long)LL*DOUT, (long long)LL*DOUT, (long long)LL*LL,
        nullptr, nullptr, nullptr);

    softmax_k<<<BB*LL, 256>>>();

    // agg = attn @ pi  per batch: M=4096, N=784, K=4096
    gemm_k<false, false, false><<<dim3(7, 32, BB), 256>>>(
        p_score, p_pi, nullptr, p_agg, LL, DIN, LL,
        (long long)LL*LL, (long long)LL*DIN, (long long)LL*DIN,
        nullptr, nullptr, nullptr);

    fold_k<<<dim3(HW/256, BB), 256>>>(b, W_w, W_b, (float*)d_out);
}

// round 3
// speedup vs baseline: 1.9695x; 1.9695x over previous
#include <cuda_runtime.h>
#include <cstdint>

#define BB 2
#define CIN 64
#define CI 16
#define HH 256
#define WWD 256
#define HW (HH*WWD)
#define LL 4096
#define DIN 784
#define DOUT 196

// ---------------- scratch (static device globals; no allocations) ----------------
__device__ float g_b1[(size_t)BB*CI*HW];
__device__ float g_b2[(size_t)BB*CI*HW];
__device__ float g_wi[(size_t)BB*LL*DIN];
__device__ float g_pi[(size_t)BB*LL*DIN];
__device__ float g_wif[(size_t)BB*LL*DOUT];
__device__ float g_xif[(size_t)BB*LL*DOUT];
__device__ float g_thr[BB*LL];
__device__ float g_bv[BB*LL];
__device__ float g_score[(size_t)BB*LL*LL];
__device__ float g_agg[(size_t)BB*LL*DIN];

// ---------------- helpers ----------------
__device__ __forceinline__ uint32_t f2tf(float f) {
    uint32_t r;
    asm("cvt.rna.tf32.f32 %0, %1;" : "=r"(r) : "f"(f));
    return r;
}
__device__ __forceinline__ void mma_tf32(float c[4], const uint32_t a[4], const uint32_t b[2]) {
    asm volatile(
        "mma.sync.aligned.m16n8k8.row.col.f32.tf32.tf32.f32 "
        "{%0,%1,%2,%3}, {%4,%5,%6,%7}, {%8,%9}, {%0,%1,%2,%3};"
        : "+f"(c[0]), "+f"(c[1]), "+f"(c[2]), "+f"(c[3])
        : "r"(a[0]), "r"(a[1]), "r"(a[2]), "r"(a[3]), "r"(b[0]), "r"(b[1]));
}

// ---------------- conv 3x3 (b -> b1), pad 1 ----------------
__global__ __launch_bounds__(256) void conv3x3_k(const float* __restrict__ bin,
    const float* __restrict__ gw, const float* __restrict__ gb)
{
    __shared__ float sw[CI*CIN*9];
    int tid = threadIdx.y*16 + threadIdx.x;
    for (int i = tid; i < CI*CIN*9; i += 256) sw[i] = gw[i];
    __syncthreads();
    int bb = blockIdx.z;
    int x = blockIdx.x*16 + threadIdx.x;
    int y = blockIdx.y*16 + threadIdx.y;
    float acc[CI];
    #pragma unroll
    for (int co = 0; co < CI; co++) acc[co] = gb[co];
    const float* bp = bin + (size_t)bb*CIN*HW;
    bool y0 = (y > 0), y2 = (y < HH-1), x0 = (x > 0), x2 = (x < WWD-1);
    for (int ci = 0; ci < CIN; ci++) {
        const float* c0 = bp + (size_t)ci*HW + y*WWD + x;
        float v[9];
        v[0] = (y0&&x0)? c0[-WWD-1]:0.f; v[1] = y0? c0[-WWD]:0.f; v[2] = (y0&&x2)? c0[-WWD+1]:0.f;
        v[3] = x0? c0[-1]:0.f;           v[4] = c0[0];            v[5] = x2? c0[1]:0.f;
        v[6] = (y2&&x0)? c0[WWD-1]:0.f;  v[7] = y2? c0[WWD]:0.f;  v[8] = (y2&&x2)? c0[WWD+1]:0.f;
        #pragma unroll
        for (int co = 0; co < CI; co++) {
            const float* w = &sw[(co*CIN+ci)*9];
            float a = acc[co];
            #pragma unroll
            for (int t = 0; t < 9; t++) a += v[t]*w[t];
            acc[co] = a;
        }
    }
    #pragma unroll
    for (int co = 0; co < CI; co++)
        g_b1[(size_t)(bb*CI+co)*HW + y*WWD + x] = acc[co];
}

// ---------------- conv 1x1 (b -> b2) ----------------
__global__ __launch_bounds__(256) void conv1x1_k(const float* __restrict__ bin,
    const float* __restrict__ tw, const float* __restrict__ tb)
{
    __shared__ float sw[CI*CIN];
    int tid = threadIdx.x;
    for (int i = tid; i < CI*CIN; i += 256) sw[i] = tw[i];
    __syncthreads();
    int p = blockIdx.x*256 + tid;
    int bb = blockIdx.y;
    const float* bp = bin + (size_t)bb*CIN*HW + p;
    float acc[CI];
    #pragma unroll
    for (int co = 0; co < CI; co++) acc[co] = tb[co];
    for (int ci = 0; ci < CIN; ci++) {
        float v = bp[(size_t)ci*HW];
        #pragma unroll
        for (int co = 0; co < CI; co++) acc[co] += v * sw[co*CIN+ci];
    }
    #pragma unroll
    for (int co = 0; co < CI; co++)
        g_b2[(size_t)(bb*CI+co)*HW + p] = acc[co];
}

// ---------------- thr/bias 7x7 stride-4 convs (padded SAME) ----------------
__global__ __launch_bounds__(256) void thrbias_k(const float* __restrict__ bin,
    const float* __restrict__ tw, const float* __restrict__ tb,
    const float* __restrict__ bw, const float* __restrict__ bwb)
{
    __shared__ float swt[CIN*49], swb[CIN*49];
    int tid = threadIdx.x;
    for (int i = tid; i < CIN*49; i += 256) { swt[i] = tw[i]; swb[i] = bw[i]; }
    __syncthreads();
    int idx = blockIdx.x*256 + tid;              // b*LL + l
    int bb = idx >> 12;
    int l = idx & (LL-1);
    int r = l >> 6, c = l & 63;
    float at = tb[0], ab = bwb[0];
    const float* bp = bin + (size_t)bb*CIN*HW;
    int ybase = r*4 - 1, xbase = c*4 - 1;        // pad top/left = 1
    for (int ci = 0; ci < CIN; ci++) {
        const float* cp = bp + (size_t)ci*HW;
        #pragma unroll
        for (int di = 0; di < 7; di++) {
            int iy = ybase + di;
            if (iy < 0 || iy >= HH) continue;
            #pragma unroll
            for (int dj = 0; dj < 7; dj++) {
                int ix = xbase + dj;
                if (ix < 0 || ix >= WWD) continue;
                float v = cp[iy*WWD + ix];
                at += v * swt[ci*49 + di*7 + dj];
                ab += v * swb[ci*49 + di*7 + dj];
            }
        }
    }
    g_thr[idx] = at;
    g_bv[idx] = ab;
}

// ---------------- patch extraction: wi from b1 (z=0), pi from b2 (z=1) ----------------
__global__ __launch_bounds__(256) void patches_k()
{
    int t = blockIdx.x*256 + threadIdx.x;        // < BB*LL*DIN
    int d = t % DIN;
    int rest = t / DIN;
    int l = rest & (LL-1);
    int bb = rest >> 12;
    int ci = d / 49, rem = d % 49;
    int di = rem / 7, dj = rem % 7;
    int r = l >> 6, c = l & 63;
    int iy = r*4 + di - 1, ix = c*4 + dj - 1;    // pad = 1 top/left
    float val = 0.f;
    if (iy >= 0 && iy < HH && ix >= 0 && ix < WWD) {
        size_t src = (size_t)(bb*CI+ci)*HW + (size_t)iy*WWD + ix;
        val = (blockIdx.z == 0) ? g_b1[src] : g_b2[src];
    }
    if (blockIdx.z == 0) g_wi[(size_t)t] = val;
    else                 g_pi[(size_t)t] = val;
}

// ---------------- TF32 tensor-core GEMM: 128x128x32 block, 8 warps, warp 64x32 ----------------
// C[M,N] = A[M,K](row-major) * B.
// TRANSB: B is [N,K] row-major (mma col-operand natural).  else: B is [K,N] row-major.
// Dual mode (C2 != null): blockIdx.z==1 switches Bm/bias/C.  Else batched with strides.
#define AST 36
#define BSTK 136
template<bool TRANSB, bool BIASRELU>
__global__ __launch_bounds__(256) void tc_gemm_k(
    const float* __restrict__ A, const float* __restrict__ Bm,
    const float* __restrict__ bias, float* __restrict__ C,
    int M, int N, int K,
    long long sA, long long sB, long long sC,
    const float* __restrict__ B2, const float* __restrict__ bias2, float* __restrict__ C2)
{
    int z = blockIdx.z;
    if (C2 != nullptr) {
        if (z == 1) { Bm = B2; bias = bias2; C = C2; }
    } else {
        A  += (size_t)z * sA;
        Bm += (size_t)z * sB;
        C  += (size_t)z * sC;
    }
    __shared__ uint32_t As[128*AST];    // [m][k] stride 36
    __shared__ uint32_t Bs[128*AST];    // TRANSB: [n][k] stride 36 ; else [k][n] stride 136

    int tid = threadIdx.x;
    int wid = tid >> 5, ln = tid & 31;
    int wr = wid >> 2, wc = wid & 3;     // warp: m-off wr*64, n-off wc*32
    int g = ln >> 2, t = ln & 3;
    int m0 = blockIdx.y * 128, n0 = blockIdx.x * 128;

    float c[4][4][4];
    #pragma unroll
    for (int i = 0; i < 4; i++)
        #pragma unroll
        for (int j = 0; j < 4; j++)
            #pragma unroll
            for (int q = 0; q < 4; q++) c[i][j][q] = 0.f;

    // loader indices
    int arow = tid >> 3;               // 0..31, +i*32
    int acol = (tid & 7) * 4;          // k offset within tile
    int bnrow = tid >> 1;              // TRANSB: n row 0..127
    int bkcol = (tid & 1) * 16;
    int bkrow = tid >> 3;              // !TRANSB: k row 0..31
    int bncol = (tid & 7) * 16;

    for (int k0 = 0; k0 < K; k0 += 32) {
        // stage global loads
        float sa[4][4];
        #pragma unroll
        for (int i = 0; i < 4; i++) {
            int m = m0 + arow + i*32;
            const float* ap = A + (size_t)m*K;
            #pragma unroll
            for (int j = 0; j < 4; j++) {
                int k = k0 + acol + j;
                sa[i][j] = (k < K) ? ap[k] : 0.f;
            }
        }
        float sb[16];
        if (TRANSB) {
            int n = n0 + bnrow;
            const float* bp = Bm + (size_t)n*K;
            #pragma unroll
            for (int j = 0; j < 16; j++) {
                int k = k0 + bkcol + j;
                sb[j] = (n < N && k < K) ? bp[k] : 0.f;
            }
        } else {
            int k = k0 + bkrow;
            const float* bp = Bm + (size_t)k*N;
            #pragma unroll
            for (int j = 0; j < 16; j++) {
                int n = n0 + bncol + j;
                sb[j] = (k < K && n < N) ? bp[n] : 0.f;
            }
        }
        __syncthreads();
        #pragma unroll
        for (int i = 0; i < 4; i++)
            #pragma unroll
            for (int j = 0; j < 4; j++)
                As[(arow + i*32)*AST + acol + j] = f2tf(sa[i][j]);
        if (TRANSB) {
            #pragma unroll
            for (int j = 0; j < 16; j++) Bs[bnrow*AST + bkcol + j] = f2tf(sb[j]);
        } else {
            #pragma unroll
            for (int j = 0; j < 16; j++) Bs[bkrow*BSTK + bncol + j] = f2tf(sb[j]);
        }
        __syncthreads();

        #pragma unroll
        for (int ks = 0; ks < 4; ks++) {
            int k = ks*8;
            uint32_t af[4][4];
            #pragma unroll
            for (int mi = 0; mi < 4; mi++) {
                int mr = wr*64 + mi*16;
                af[mi][0] = As[(mr+g  )*AST + k+t  ];
                af[mi][1] = As[(mr+g+8)*AST + k+t  ];
                af[mi][2] = As[(mr+g  )*AST + k+t+4];
                af[mi][3] = As[(mr+g+8)*AST + k+t+4];
            }
            uint32_t bf[4][2];
            #pragma unroll
            for (int ni = 0; ni < 4; ni++) {
                int nc = wc*32 + ni*8 + g;
                if (TRANSB) {
                    bf[ni][0] = Bs[nc*AST + k+t  ];
                    bf[ni][1] = Bs[nc*AST + k+t+4];
                } else {
                    bf[ni][0] = Bs[(k+t  )*BSTK + nc];
                    bf[ni][1] = Bs[(k+t+4)*BSTK + nc];
                }
            }
            #pragma unroll
            for (int mi = 0; mi < 4; mi++)
                #pragma unroll
                for (int ni = 0; ni < 4; ni++)
                    mma_tf32(c[mi][ni], af[mi], bf[ni]);
        }
        __syncthreads();
    }

    // epilogue
    #pragma unroll
    for (int mi = 0; mi < 4; mi++) {
        int r0 = m0 + wr*64 + mi*16 + g;
        #pragma unroll
        for (int ni = 0; ni < 4; ni++) {
            int nb = n0 + wc*32 + ni*8 + 2*t;
            #pragma unroll
            for (int h = 0; h < 2; h++) {
                int n = nb + h;
                if (n >= N) continue;
                float v0 = c[mi][ni][h];
                float v1 = c[mi][ni][2+h];
                if (BIASRELU) {
                    float bv = bias[n];
                    v0 = fmaxf(v0 + bv, 0.f);
                    v1 = fmaxf(v1 + bv, 0.f);
                }
                C[(size_t)r0*N + n]     = v0;
                C[(size_t)(r0+8)*N + n] = v1;
            }
        }
    }
}

// ---------------- masked softmax + renorm, in-place over g_score rows ----------------
__global__ __launch_bounds__(256) void softmax_k()
{
    __shared__ float sh0[8], sh1[8];
    int row = blockIdx.x;                       // b*LL + l
    int tid = threadIdx.x;
    float thr = g_thr[row], bs = g_bv[row];
    float* S = g_score + (size_t)row*LL;
    float g[16];
    unsigned mb = 0;
    float lmax = -3.4e38f;
    #pragma unroll
    for (int i = 0; i < 16; i++) {
        float s = S[i*256 + tid];
        bool m = (s >= thr);
        float gg = (m ? s : 0.f) + bs;
        if (m) mb |= (1u << i);
        g[i] = gg;
        lmax = fmaxf(lmax, gg);
    }
    float v = lmax;
    #pragma unroll
    for (int o = 16; o > 0; o >>= 1) v = fmaxf(v, __shfl_xor_sync(0xffffffffu, v, o));
    if ((tid & 31) == 0) sh0[tid >> 5] = v;
    __syncthreads();
    float M = sh0[0];
    #pragma unroll
    for (int i = 1; i < 8; i++) M = fmaxf(M, sh0[i]);
    __syncthreads();
    float z = 0.f, a = 0.f;
    #pragma unroll
    for (int i = 0; i < 16; i++) {
        float e = __expf(10.f * (g[i] - M));
        z += e;
        float me = ((mb >> i) & 1u) ? e : 0.f;
        a += me;
        g[i] = me;
    }
    float vz = z, va = a;
    #pragma unroll
    for (int o = 16; o > 0; o >>= 1) {
        vz += __shfl_xor_sync(0xffffffffu, vz, o);
        va += __shfl_xor_sync(0xffffffffu, va, o);
    }
    if ((tid & 31) == 0) { sh0[tid >> 5] = vz; sh1[tid >> 5] = va; }
    __syncthreads();
    float Z = 0.f, A = 0.f;
    #pragma unroll
    for (int i = 0; i < 8; i++) { Z += sh0[i]; A += sh1[i]; }
    float inv = 1.f / (A + 1e-8f * Z);
    #pragma unroll
    for (int i = 0; i < 16; i++) S[i*256 + tid] = g[i] * inv;
}

// ---------------- fold (overlap-add gather / count) + 1x1 conv + residual ----------------
__global__ __launch_bounds__(256) void fold_k(const float* __restrict__ bin,
    const float* __restrict__ Ww, const float* __restrict__ Wb,
    float* __restrict__ out)
{
    __shared__ float sw[CIN*CI];
    int tid = threadIdx.x;
    for (int i = tid; i < CIN*CI; i += 256) sw[i] = Ww[i];
    __syncthreads();
    int p = blockIdx.x*256 + tid;
    int bb = blockIdx.y;
    int y = p >> 8, x = p & 255;
    int u = y + 1, v = x + 1;                  // padded coords (crop offset 1)
    int rlo = (u-3) >> 2; if (rlo < 0) rlo = 0;
    int rhi = u >> 2;     if (rhi > 63) rhi = 63;
    int clo = (v-3) >> 2; if (clo < 0) clo = 0;
    int chi = v >> 2;     if (chi > 63) chi = 63;
    float zi[CI];
    #pragma unroll
    for (int ci = 0; ci < CI; ci++) zi[ci] = 0.f;
    for (int r = rlo; r <= rhi; r++) {
        int di = u - r*4;
        for (int c = clo; c <= chi; c++) {
            int dj = v - c*4;
            const float* ap = g_agg + ((size_t)bb*LL + (r<<6) + c)*DIN + di*7 + dj;
            #pragma unroll
            for (int ci = 0; ci < CI; ci++) zi[ci] += ap[ci*49];
        }
    }
    float inv = 1.f / (float)((rhi-rlo+1)*(chi-clo+1));
    #pragma unroll
    for (int ci = 0; ci < CI; ci++) zi[ci] *= inv;
    const float* bp = bin + (size_t)bb*CIN*HW + p;
    float* op = out + (size_t)bb*CIN*HW + p;
    #pragma unroll 4
    for (int co = 0; co < CIN; co++) {
        float a = bp[(size_t)co*HW] + Wb[co];
        const float* w = &sw[co*CI];
        #pragma unroll
        for (int ci = 0; ci < CI; ci++) a += w[ci]*zi[ci];
        op[(size_t)co*HW] = a;
    }
}

// ---------------- launch ----------------
extern "C" void kernel_launch(void* const* d_in, const int* in_sizes, int n_in,
                              void* d_out, int out_size)
{
    const float* b       = (const float*)d_in[0];
    const float* g_w     = (const float*)d_in[1];
    const float* g_bias  = (const float*)d_in[2];
    const float* theta_w = (const float*)d_in[3];
    const float* theta_b = (const float*)d_in[4];
    const float* W_w     = (const float*)d_in[5];
    const float* W_b     = (const float*)d_in[6];
    const float* fc1_w   = (const float*)d_in[7];
    const float* fc1_b   = (const float*)d_in[8];
    const float* fc2_w   = (const float*)d_in[9];
    const float* fc2_b   = (const float*)d_in[10];
    const float* thr_w   = (const float*)d_in[11];
    const float* thr_b   = (const float*)d_in[12];
    const float* bias_w  = (const float*)d_in[13];
    const float* bias_b  = (const float*)d_in[14];

    float *p_wi, *p_pi, *p_wif, *p_xif, *p_score, *p_agg;
    cudaGetSymbolAddress((void**)&p_wi,    g_wi);
    cudaGetSymbolAddress((void**)&p_pi,    g_pi);
    cudaGetSymbolAddress((void**)&p_wif,   g_wif);
    cudaGetSymbolAddress((void**)&p_xif,   g_xif);
    cudaGetSymbolAddress((void**)&p_score, g_score);
    cudaGetSymbolAddress((void**)&p_agg,   g_agg);

    conv3x3_k<<<dim3(16,16,BB), dim3(16,16)>>>(b, g_w, g_bias);
    conv1x1_k<<<dim3(HW/256, BB), 256>>>(b, theta_w, theta_b);
    thrbias_k<<<(BB*LL)/256, 256>>>(b, thr_w, thr_b, bias_w, bias_b);
    patches_k<<<dim3((BB*LL*DIN)/256, 1, 2), 256>>>();

    // fc1 & fc2 fused via dual mode: M=8192, N=196, K=784, bias+relu, TF32 TC
    tc_gemm_k<true, true><<<dim3(2, 64, 2), 256>>>(
        p_wi, fc1_w, fc1_b, p_wif, BB*LL, DOUT, DIN,
        0, 0, 0, fc2_w, fc2_b, p_xif);

    // score = wif @ xif^T per batch: M=N=4096, K=196, TF32 TC
    tc_gemm_k<true, false><<<dim3(32, 32, BB), 256>>>(
        p_wif, p_xif, nullptr, p_score, LL, LL, DOUT,
        (long long)LL*DOUT, (long long)LL*DOUT, (long long)LL*LL,
        nullptr, nullptr, nullptr);

    softmax_k<<<BB*LL, 256>>>();

    // agg = attn @ pi per batch: M=4096, N=784, K=4096, TF32 TC
    tc_gemm_k<false, false><<<dim3(7, 32, BB), 256>>>(
        p_score, p_pi, nullptr, p_agg, LL, DIN, LL,
        (long long)LL*LL, (long long)LL*DIN, (long long)LL*DIN,
        nullptr, nullptr, nullptr);

    fold_k<<<dim3(HW/256, BB), 256>>>(b, W_w, W_b, (float*)d_out);
}